// round 1
// baseline (speedup 1.0000x reference)
#include <cuda_runtime.h>
#include <math.h>

// Block-diagonal multi-head SDPA, fp32 flash-attention style.
// Shapes: Q/K/V [8192, 2048] fp32 (8 segs x 1024 tokens, 16 heads x 128 dim)
// Out: [1, 16, 8192, 128] fp32.

#define HEADS   16
#define DHEAD   128
#define NSEG    8
#define SEGLEN  1024
#define HID     2048
#define TTOT    (NSEG * SEGLEN)

#define BM      64
#define BN      64
#define NKT     (SEGLEN / BN)     // 16 KV tiles per segment
#define NTHREADS 256

#define KV_STRIDE 132             // 128 + 4 pad (float units), keeps float4 alignment
#define PS_STRIDE 65              // 64 + 1 pad

// shared mem: Qs + Ks + Vs (each BM/BN x KV_STRIDE) + Ps (BN x PS_STRIDE)
#define SMEM_FLOATS (3 * 64 * KV_STRIDE + 64 * PS_STRIDE)
#define SMEM_BYTES  (SMEM_FLOATS * 4)

__global__ __launch_bounds__(NTHREADS, 1)
void fa_fp32_kernel(const float* __restrict__ Q,
                    const float* __restrict__ K,
                    const float* __restrict__ V,
                    float* __restrict__ O)
{
    extern __shared__ float sm[];
    float* Qs = sm;                         // [64][132]
    float* Ks = Qs + 64 * KV_STRIDE;        // [64][132]
    float* Vs = Ks + 64 * KV_STRIDE;        // [64][132]
    float* Ps = Vs + 64 * KV_STRIDE;        // [64][65]  (Ps[n][m])

    const int tid = threadIdx.x;
    const int tx  = tid & 15;               // 0..15: owns n in {tx+16j}, d in {4tx, 64+4tx}
    const int ty  = tid >> 4;               // 0..15: owns m rows ty*4 .. ty*4+3

    const int mt = blockIdx.x;              // m-tile within segment (0..15)
    const int h  = blockIdx.y;              // head (0..15)
    const int sg = blockIdx.z;              // segment (0..7)

    const int qrow0 = sg * SEGLEN + mt * BM;  // global token row of this Q tile
    const int col0  = h * DHEAD;              // column offset within hidden dim

    // ---- load Q tile (64 x 128) into smem, coalesced ----
    #pragma unroll
    for (int it = 0; it < 8; ++it) {
        int idx = tid + it * NTHREADS;      // 0..2047 float4 ids
        int r   = idx >> 5;                 // row 0..63
        int d4  = idx & 31;                 // float4 col 0..31
        float4 v = *reinterpret_cast<const float4*>(
            &Q[(size_t)(qrow0 + r) * HID + col0 + 4 * d4]);
        *reinterpret_cast<float4*>(&Qs[r * KV_STRIDE + 4 * d4]) = v;
    }

    // ---- accumulators & softmax state ----
    float acc[4][2][4];                     // [m-row][d-chunk][d-elem]
    #pragma unroll
    for (int i = 0; i < 4; ++i)
        #pragma unroll
        for (int c = 0; c < 2; ++c)
            #pragma unroll
            for (int k = 0; k < 4; ++k)
                acc[i][c][k] = 0.0f;

    float mi[4], li[4];
    #pragma unroll
    for (int i = 0; i < 4; ++i) { mi[i] = -INFINITY; li[i] = 0.0f; }

    const float scale = 0.08838834764831845f;  // 1/sqrt(128)

    for (int kb = 0; kb < NKT; ++kb) {
        __syncthreads();   // previous PV done reading Ks/Vs/Ps

        // ---- load K,V tiles (64 x 128 each), coalesced ----
        const int krow0 = sg * SEGLEN + kb * BN;
        #pragma unroll
        for (int it = 0; it < 8; ++it) {
            int idx = tid + it * NTHREADS;
            int r   = idx >> 5;
            int d4  = idx & 31;
            *reinterpret_cast<float4*>(&Ks[r * KV_STRIDE + 4 * d4]) =
                *reinterpret_cast<const float4*>(
                    &K[(size_t)(krow0 + r) * HID + col0 + 4 * d4]);
            *reinterpret_cast<float4*>(&Vs[r * KV_STRIDE + 4 * d4]) =
                *reinterpret_cast<const float4*>(
                    &V[(size_t)(krow0 + r) * HID + col0 + 4 * d4]);
        }
        __syncthreads();

        // ---- QK^T: s[i][j] = Q[ty*4+i] . K[tx+16j] ----
        float s[4][4];
        #pragma unroll
        for (int i = 0; i < 4; ++i)
            #pragma unroll
            for (int j = 0; j < 4; ++j)
                s[i][j] = 0.0f;

        #pragma unroll 4
        for (int dd = 0; dd < DHEAD; dd += 4) {
            float4 qf[4], kf[4];
            #pragma unroll
            for (int i = 0; i < 4; ++i)
                qf[i] = *reinterpret_cast<const float4*>(
                    &Qs[(ty * 4 + i) * KV_STRIDE + dd]);
            #pragma unroll
            for (int j = 0; j < 4; ++j)
                kf[j] = *reinterpret_cast<const float4*>(
                    &Ks[(tx + 16 * j) * KV_STRIDE + dd]);
            #pragma unroll
            for (int i = 0; i < 4; ++i)
                #pragma unroll
                for (int j = 0; j < 4; ++j) {
                    s[i][j] += qf[i].x * kf[j].x;
                    s[i][j] += qf[i].y * kf[j].y;
                    s[i][j] += qf[i].z * kf[j].z;
                    s[i][j] += qf[i].w * kf[j].w;
                }
        }

        // ---- online softmax (rows reduce across the 16 tx lanes in-warp) ----
        #pragma unroll
        for (int i = 0; i < 4; ++i) {
            #pragma unroll
            for (int j = 0; j < 4; ++j) s[i][j] *= scale;

            float tm = fmaxf(fmaxf(s[i][0], s[i][1]), fmaxf(s[i][2], s[i][3]));
            #pragma unroll
            for (int o = 1; o < 16; o <<= 1)
                tm = fmaxf(tm, __shfl_xor_sync(0xffffffffu, tm, o));

            float mnew  = fmaxf(mi[i], tm);
            float alpha = __expf(mi[i] - mnew);
            mi[i] = mnew;

            float psum = 0.0f;
            #pragma unroll
            for (int j = 0; j < 4; ++j) {
                s[i][j] = __expf(s[i][j] - mnew);
                psum += s[i][j];
            }
            #pragma unroll
            for (int o = 1; o < 16; o <<= 1)
                psum += __shfl_xor_sync(0xffffffffu, psum, o);

            li[i] = li[i] * alpha + psum;

            #pragma unroll
            for (int c = 0; c < 2; ++c)
                #pragma unroll
                for (int k = 0; k < 4; ++k)
                    acc[i][c][k] *= alpha;

            // stage P transposed: Ps[n][m]
            #pragma unroll
            for (int j = 0; j < 4; ++j)
                Ps[(tx + 16 * j) * PS_STRIDE + ty * 4 + i] = s[i][j];
        }
        __syncthreads();

        // ---- PV: acc[i][c][*] += P[m][n] * V[n][d] ----
        #pragma unroll 4
        for (int n = 0; n < BN; ++n) {
            float4 v0 = *reinterpret_cast<const float4*>(
                &Vs[n * KV_STRIDE + 4 * tx]);
            float4 v1 = *reinterpret_cast<const float4*>(
                &Vs[n * KV_STRIDE + 64 + 4 * tx]);
            #pragma unroll
            for (int i = 0; i < 4; ++i) {
                float p = Ps[n * PS_STRIDE + ty * 4 + i];
                acc[i][0][0] += p * v0.x;
                acc[i][0][1] += p * v0.y;
                acc[i][0][2] += p * v0.z;
                acc[i][0][3] += p * v0.w;
                acc[i][1][0] += p * v1.x;
                acc[i][1][1] += p * v1.y;
                acc[i][1][2] += p * v1.z;
                acc[i][1][3] += p * v1.w;
            }
        }
    }

    // ---- epilogue: normalize by li, write out [1,H,T,D] ----
    #pragma unroll
    for (int i = 0; i < 4; ++i) {
        float inv = 1.0f / li[i];
        int t = qrow0 + ty * 4 + i;            // global token index
        size_t base = (size_t)h * TTOT * DHEAD + (size_t)t * DHEAD;
        float4 o0, o1;
        o0.x = acc[i][0][0] * inv; o0.y = acc[i][0][1] * inv;
        o0.z = acc[i][0][2] * inv; o0.w = acc[i][0][3] * inv;
        o1.x = acc[i][1][0] * inv; o1.y = acc[i][1][1] * inv;
        o1.z = acc[i][1][2] * inv; o1.w = acc[i][1][3] * inv;
        *reinterpret_cast<float4*>(&O[base + 4 * tx])      = o0;
        *reinterpret_cast<float4*>(&O[base + 64 + 4 * tx]) = o1;
    }
}

extern "C" void kernel_launch(void* const* d_in, const int* in_sizes, int n_in,
                              void* d_out, int out_size)
{
    const float* q = (const float*)d_in[0];
    const float* k = (const float*)d_in[1];
    const float* v = (const float*)d_in[2];
    float* o = (float*)d_out;

    cudaFuncSetAttribute(fa_fp32_kernel,
                         cudaFuncAttributeMaxDynamicSharedMemorySize,
                         SMEM_BYTES);

    dim3 grid(SEGLEN / BM, HEADS, NSEG);   // (16, 16, 8) = 2048 blocks
    fa_fp32_kernel<<<grid, NTHREADS, SMEM_BYTES>>>(q, k, v, o);
}